// round 15
// baseline (speedup 1.0000x reference)
#include <cuda_runtime.h>
#include <cuda_bf16.h>
#include <mma.h>
#include <cstdint>

using namespace nvcuda;

typedef uint32_t u32;
typedef unsigned short u16;

#define NN 90
#define HD 128
#define NT 512

// ---------------- device scratch: weight products + bf16 split tiles ---------
__device__ __align__(16) float g_U1[NN * HD];   // W0 @ Wr1
__device__ __align__(16) float g_V1[NN * HD];   // W0 @ W1
__device__ __align__(16) float g_P [NN * HD];   // U1 @ W2
__device__ __align__(16) float g_Q [NN * HD];   // U1 @ Wr2
__device__ __align__(16) float g_u1[HD];        // Wr1^T b0 + br1 ; later: b1
__device__ __align__(16) float g_v1[HD];        // W1^T b0
__device__ __align__(16) float g_p [HD];        // W2^T u1
__device__ __align__(16) float g_q [HD];        // Wr2^T u1 + b2 + br2
// row-major [128 x 128] bf16 hi/lo operand tiles (rows k >= K zeroed)
__device__ __align__(16) u16 t_V1h[128*128], t_V1l[128*128];
__device__ __align__(16) u16 t_Ph [128*128], t_Pl [128*128];
__device__ __align__(16) u16 t_W2h[128*128], t_W2l[128*128];

__device__ __forceinline__ void bfsplit1(float x, u16& h, u16& l) {
    __nv_bfloat16 bh = __float2bfloat16_rn(x);
    h = __bfloat16_as_ushort(bh);
    l = __bfloat16_as_ushort(__float2bfloat16_rn(x - __bfloat162float(bh)));
}

// ---------------- precompute kernels -----------------------------------------
__global__ void pre1_kernel(const float* __restrict__ W0,
                            const float* __restrict__ Wr1,
                            const float* __restrict__ W1,
                            const float* __restrict__ b0,
                            const float* __restrict__ br1)
{
    __shared__ float s[HD];
    const int m = blockIdx.x / (NN + 1);
    const int i = blockIdx.x % (NN + 1);
    const int t = threadIdx.x;
    const float* M = m ? W1 : Wr1;
    const float* src = (i < NN) ? (W0 + i * HD) : b0;
    s[t] = src[t];
    __syncthreads();
    float acc = 0.f;
#pragma unroll 8
    for (int k = 0; k < HD; ++k) acc = fmaf(s[k], M[k * HD + t], acc);
    if (i < NN) (m ? g_V1 : g_U1)[i * HD + t] = acc;
    else if (m) g_v1[t] = acc;
    else        g_u1[t] = acc + br1[t];
}

__global__ void pre2_kernel(const float* __restrict__ W2,
                            const float* __restrict__ Wr2,
                            const float* __restrict__ b2,
                            const float* __restrict__ br2)
{
    __shared__ float s[HD];
    const int m = blockIdx.x / (NN + 1);
    const int i = blockIdx.x % (NN + 1);
    const int t = threadIdx.x;
    const float* M = m ? Wr2 : W2;
    const float* src = (i < NN) ? (g_U1 + i * HD) : g_u1;
    s[t] = src[t];
    __syncthreads();
    float acc = 0.f;
#pragma unroll 8
    for (int k = 0; k < HD; ++k) acc = fmaf(s[k], M[k * HD + t], acc);
    if (i < NN) (m ? g_Q : g_P)[i * HD + t] = acc;
    else if (m) g_q[t] = acc + b2[t] + br2[t];
    else        g_p[t] = acc;
}

// build row-major bf16 hi/lo tiles; 0=V1 (K=90), 1=P (K=90), 2=W2 (K=128)
__global__ void pre_tiles_kernel(const float* __restrict__ W2)
{
    const int which = blockIdx.x;
    const float* M = (which == 0) ? g_V1 : (which == 1) ? g_P : W2;
    const int K = (which == 2) ? 128 : NN;
    u16* th = (which == 0) ? t_V1h : (which == 1) ? t_Ph : t_W2h;
    u16* tl = (which == 0) ? t_V1l : (which == 1) ? t_Pl : t_W2l;
    for (int e = threadIdx.x; e < 128 * 128; e += blockDim.x) {
        int k = e >> 7;
        float v = (k < K) ? M[e] : 0.f;   // M row-major [K x 128]
        u16 h, l; bfsplit1(v, h, l);
        th[e] = h; tl[e] = l;
    }
}

// stage b1 into g_u1 (dead after pre2; launched after pre2)
__global__ void pre_b1_kernel(const float* __restrict__ b1) {
    g_u1[threadIdx.x] = b1[threadIdx.x];
}

// ---------------- main WMMA kernel -------------------------------------------
// dynamic smem layout (bytes)
#define OFF_AH 0          // A hi    [96 x 96]  u16  (18432 B)
#define OFF_AL 18432      // A lo
#define OFF_BH 36864      // B hi    [128 x 128] u16 (32768 B)
#define OFF_BL 69632      // B lo
#define OFF_LH 102400     // L hi    [96 x 128] u16  (24576 B)  (R3 / Y)
#define OFF_LL 126976     // L lo
#define OFF_D  151552     // D stage [96 x 128] fp32 (49152 B)
#define SM_TOTAL 200704
#define A_LD 96

typedef wmma::fragment<wmma::matrix_a, 16, 16, 16, __nv_bfloat16, wmma::row_major> FragA;
typedef wmma::fragment<wmma::matrix_b, 16, 16, 16, __nv_bfloat16, wmma::row_major> FragBR;
typedef wmma::fragment<wmma::matrix_b, 16, 16, 16, __nv_bfloat16, wmma::col_major> FragBC;
typedef wmma::fragment<wmma::accumulator, 16, 16, 16, float> FragC;

// one GEMM stage: acc[3] over rows mrow0..mrow0+47, cols ncol0..ncol0+15
// COLB=false: B row-major [K x N] (ldb=128). COLB=true: B col-major view of
// a row-major [N x K] array (ldb=128) -> computes A @ B^T.
template<int NKT, bool COLB>
__device__ __forceinline__ void mma_stage(
    FragC* acc,
    const u16* Ah, const u16* Al, int lda,
    const u16* Bh, const u16* Bl,
    int mrow0, int ncol0)
{
#pragma unroll 1
    for (int kt = 0; kt < NKT; ++kt) {
        if (COLB) {
            FragBC bh, bl;
            const __nv_bfloat16* bhp = (const __nv_bfloat16*)Bh + ncol0 * 128 + kt * 16;
            const __nv_bfloat16* blp = (const __nv_bfloat16*)Bl + ncol0 * 128 + kt * 16;
            wmma::load_matrix_sync(bh, bhp, 128);
            wmma::load_matrix_sync(bl, blp, 128);
#pragma unroll
            for (int mt = 0; mt < 3; ++mt) {
                FragA ah, al;
                const __nv_bfloat16* ap = (const __nv_bfloat16*)Ah + (mrow0 + mt * 16) * lda + kt * 16;
                const __nv_bfloat16* alp = (const __nv_bfloat16*)Al + (mrow0 + mt * 16) * lda + kt * 16;
                wmma::load_matrix_sync(ah, ap, lda);
                wmma::load_matrix_sync(al, alp, lda);
                wmma::mma_sync(acc[mt], ah, bh, acc[mt]);
                wmma::mma_sync(acc[mt], ah, bl, acc[mt]);
                wmma::mma_sync(acc[mt], al, bh, acc[mt]);
            }
        } else {
            FragBR bh, bl;
            const __nv_bfloat16* bhp = (const __nv_bfloat16*)Bh + kt * 16 * 128 + ncol0;
            const __nv_bfloat16* blp = (const __nv_bfloat16*)Bl + kt * 16 * 128 + ncol0;
            wmma::load_matrix_sync(bh, bhp, 128);
            wmma::load_matrix_sync(bl, blp, 128);
#pragma unroll
            for (int mt = 0; mt < 3; ++mt) {
                FragA ah, al;
                const __nv_bfloat16* ap = (const __nv_bfloat16*)Ah + (mrow0 + mt * 16) * lda + kt * 16;
                const __nv_bfloat16* alp = (const __nv_bfloat16*)Al + (mrow0 + mt * 16) * lda + kt * 16;
                wmma::load_matrix_sync(ah, ap, lda);
                wmma::load_matrix_sync(al, alp, lda);
                wmma::mma_sync(acc[mt], ah, bh, acc[mt]);
                wmma::mma_sync(acc[mt], ah, bl, acc[mt]);
                wmma::mma_sync(acc[mt], al, bh, acc[mt]);
            }
        }
    }
}

__device__ __forceinline__ void store_acc(FragC* acc, float* D, int mrow0, int ncol0)
{
#pragma unroll
    for (int mt = 0; mt < 3; ++mt)
        wmma::store_matrix_sync(D + (mrow0 + mt * 16) * 128 + ncol0, acc[mt],
                                128, wmma::mem_row_major);
}

__global__ void __launch_bounds__(NT, 1)
graphcnn_wmma(const float* __restrict__ adj, float* __restrict__ out)
{
    extern __shared__ char sm[];
    u16* Ah = (u16*)(sm + OFF_AH);
    u16* Al = (u16*)(sm + OFF_AL);
    u16* Bh = (u16*)(sm + OFF_BH);
    u16* Bl = (u16*)(sm + OFF_BL);
    u16* Lh = (u16*)(sm + OFF_LH);
    u16* Ll = (u16*)(sm + OFF_LL);
    float* D = (float*)(sm + OFF_D);
    __shared__ float a_s[96], v1s[HD], b1s[HD], ps[HD], qvs[HD];

    const int tid = threadIdx.x;
    const int w = tid >> 5;
    const int lane = tid & 31;
    const int b = blockIdx.x;

    // warp tiling for G1-G5: 8 n-tiles x 2 m-groups (3 m-tiles each)
    const int ncol0 = (w & 7) * 16;
    const int mrow0 = (w >> 3) * 48;

    if (tid < HD) {
        v1s[tid] = g_v1[tid];
        b1s[tid] = g_u1[tid];    // b1 (staged by pre_b1_kernel)
        ps[tid]  = g_p[tid];
        qvs[tid] = g_q[tid];
    }

    // A bf16 split tiles [96 x 96], zero-padded
    const float* ag = adj + (size_t)b * (NN * NN);
    for (int e = tid; e < 96 * 96; e += NT) {
        int r = e / 96, c = e - r * 96;
        float v = (r < NN && c < NN) ? ag[r * NN + c] : 0.f;
        u16 h, l; bfsplit1(v, h, l);
        Ah[e] = h; Al[e] = l;
    }
    // rowsums, warp per row
    for (int row = w; row < NN; row += 16) {
        const float* ar = ag + row * NN;
        float s = ar[lane] + ar[lane + 32] + ((lane < 26) ? ar[lane + 64] : 0.f);
#pragma unroll
        for (int o = 16; o; o >>= 1) s += __shfl_xor_sync(~0u, s, o);
        if (lane == 0) a_s[row] = s;
    }
    // V1 tiles -> B
    {
        const float4* s1 = (const float4*)t_V1h;
        const float4* s2 = (const float4*)t_V1l;
        float4* d1 = (float4*)Bh; float4* d2 = (float4*)Bl;
        for (int e = tid; e < 2048; e += NT) { d1[e] = s1[e]; d2[e] = s2[e]; }
    }
    __syncthreads();

    FragC acc[3];

    // ---- G1: D = A @ V1 (K=96) ----
    for (int mt = 0; mt < 3; ++mt) wmma::fill_fragment(acc[mt], 0.f);
    mma_stage<6, false>(acc, Ah, Al, A_LD, Bh, Bl, mrow0, ncol0);
    store_acc(acc, D, mrow0, ncol0);
    __syncthreads();
    // E1: B1 -> B operand tiles (rows 90..95 zero)
    for (int e = tid; e < 96 * 128; e += NT) {
        int r = e >> 7;
        float v = (r < NN) ? D[e] : 0.f;
        u16 h, l; bfsplit1(v, h, l);
        Bh[e] = h; Bl[e] = l;
    }
    __syncthreads();

    // ---- G2: D = A @ B1 (K=96) ----
    for (int mt = 0; mt < 3; ++mt) wmma::fill_fragment(acc[mt], 0.f);
    mma_stage<6, false>(acc, Ah, Al, A_LD, Bh, Bl, mrow0, ncol0);
    store_acc(acc, D, mrow0, ncol0);
    __syncthreads();
    // E2: R3 = relu(D + a*v1 + b1) -> L ; copy W2 -> B
    for (int e = tid; e < 96 * 128; e += NT) {
        int r = e >> 7, c = e & 127;
        float v = (r < NN) ? fmaxf(D[e] + fmaf(a_s[r], v1s[c], b1s[c]), 0.f) : 0.f;
        u16 h, l; bfsplit1(v, h, l);
        Lh[e] = h; Ll[e] = l;
    }
    {
        const float4* s1 = (const float4*)t_W2h;
        const float4* s2 = (const float4*)t_W2l;
        float4* d1 = (float4*)Bh; float4* d2 = (float4*)Bl;
        for (int e = tid; e < 2048; e += NT) { d1[e] = s1[e]; d2[e] = s2[e]; }
    }
    __syncthreads();

    // ---- G3: acc = R3 @ W2 (K=128), kept in registers ----
    for (int mt = 0; mt < 3; ++mt) wmma::fill_fragment(acc[mt], 0.f);
    mma_stage<8, false>(acc, Lh, Ll, HD, Bh, Bl, mrow0, ncol0);
    __syncthreads();               // all warps done reading B (W2)
    // copy P -> B
    {
        const float4* s1 = (const float4*)t_Ph;
        const float4* s2 = (const float4*)t_Pl;
        float4* d1 = (float4*)Bh; float4* d2 = (float4*)Bl;
        for (int e = tid; e < 2048; e += NT) { d1[e] = s1[e]; d2[e] = s2[e]; }
    }
    __syncthreads();

    // ---- G4: acc += A @ P (K=96) ----
    mma_stage<6, false>(acc, Ah, Al, A_LD, Bh, Bl, mrow0, ncol0);
    store_acc(acc, D, mrow0, ncol0);
    __syncthreads();
    // E4: C = D + Q -> B operand tiles
    for (int e = tid; e < 96 * 128; e += NT) {
        int r = e >> 7, c = e & 127;
        float v = (r < NN) ? (D[e] + g_Q[r * HD + c]) : 0.f;
        u16 h, l; bfsplit1(v, h, l);
        Bh[e] = h; Bl[e] = l;
    }
    __syncthreads();

    // ---- G5: D = A @ C (K=96) ----
    for (int mt = 0; mt < 3; ++mt) wmma::fill_fragment(acc[mt], 0.f);
    mma_stage<6, false>(acc, Ah, Al, A_LD, Bh, Bl, mrow0, ncol0);
    store_acc(acc, D, mrow0, ncol0);
    __syncthreads();
    // E5: Y = relu(D + a*p + q) -> L (rows 90..95 zero)
    for (int e = tid; e < 96 * 128; e += NT) {
        int r = e >> 7, c = e & 127;
        float v = (r < NN) ? fmaxf(D[e] + fmaf(a_s[r], ps[c], qvs[c]), 0.f) : 0.f;
        u16 h, l; bfsplit1(v, h, l);
        Lh[e] = h; Ll[e] = l;
    }
    __syncthreads();

    // ---- G6: Z = Y @ Y^T (K=128, N=96): B = col-major view of Y ----
    if (w < 12) {
        const int n6 = (w % 6) * 16;
        const int m6 = (w / 6) * 48;
        for (int mt = 0; mt < 3; ++mt) wmma::fill_fragment(acc[mt], 0.f);
        mma_stage<8, true>(acc, Lh, Ll, HD, Lh, Ll, m6, n6);
        store_acc(acc, D, m6, n6);
    }
    __syncthreads();

    // E6: writeout
    float* ob = out + (size_t)b * (NN * NN);
    for (int idx = tid; idx < NN * NN; idx += NT) {
        int i = idx / NN, j = idx - i * NN;
        ob[idx] = D[i * 128 + j];
    }
}

extern "C" void kernel_launch(void* const* d_in, const int* in_sizes, int n_in,
                              void* d_out, int out_size) {
    const float* adj = (const float*)d_in[0];
    const float* W0  = (const float*)d_in[1];
    const float* b0  = (const float*)d_in[2];
    const float* W1  = (const float*)d_in[3];
    const float* b1  = (const float*)d_in[4];
    const float* W2  = (const float*)d_in[5];
    const float* b2  = (const float*)d_in[6];
    const float* Wr1 = (const float*)d_in[7];
    const float* br1 = (const float*)d_in[8];
    const float* Wr2 = (const float*)d_in[9];
    const float* br2 = (const float*)d_in[10];
    float* out = (float*)d_out;

    const int B = in_sizes[0] / (NN * NN);

    pre1_kernel<<<2 * (NN + 1), HD>>>(W0, Wr1, W1, b0, br1);
    pre2_kernel<<<2 * (NN + 1), HD>>>(W2, Wr2, b2, br2);
    pre_tiles_kernel<<<3, 256>>>(W2);
    pre_b1_kernel<<<1, HD>>>(b1);   // g_u1 <- b1 (dead after pre2)

    cudaFuncSetAttribute(graphcnn_wmma,
                         cudaFuncAttributeMaxDynamicSharedMemorySize, SM_TOTAL);
    graphcnn_wmma<<<B, NT, SM_TOTAL>>>(adj, out);
}

// round 16
// speedup vs baseline: 2.0703x; 2.0703x over previous
#include <cuda_runtime.h>

typedef unsigned long long u64;

#define NN 90
#define HD 128
#define NTHREADS 512     // 16 warps: 10 x 6 rows + 6 x 5 rows = 90
#define ZS_LD 92

// smem layout (float offsets)
#define A_LD 92          // 90-float rows padded to 92 for 16B alignment
#define OFF_A  0         // 90*92  = 8280   (A, later Zs 90x92)
#define OFF_AS 8280      // a[90] rowsums (pad to 96)
#define OFF_B1 8376      // 90*128 = 11520
#define OFF_B2 19896     // 90*128 = 11520
#define OFF_Y  31416     // 90*132 = 11880 (Y row-major, padded)
#define OFF_YT 43296     // 128*91 = 11648 (Y transposed)
#define SMEM_FLOATS 54944
#define Y_LD 132
#define YT_LD 91

// ---------------- precomputed weight products (device scratch) --------------
__device__ __align__(16) float g_U1[NN * HD];   // W0 @ Wr1
__device__ __align__(16) float g_V1[NN * HD];   // W0 @ W1
__device__ __align__(16) float g_P [NN * HD];   // U1 @ W2
__device__ __align__(16) float g_Q [NN * HD];   // U1 @ Wr2
__device__ __align__(16) float g_u1[HD];        // Wr1^T b0 + br1
__device__ __align__(16) float g_v1[HD];        // W1^T b0
__device__ __align__(16) float g_p [HD];        // W2^T u1
__device__ __align__(16) float g_q [HD];        // Wr2^T u1 + b2 + br2

__global__ void pre1_kernel(const float* __restrict__ W0,
                            const float* __restrict__ Wr1,
                            const float* __restrict__ W1,
                            const float* __restrict__ b0,
                            const float* __restrict__ br1)
{
    __shared__ float s[HD];
    const int m = blockIdx.x / (NN + 1);    // 0 -> U1/u1 (Wr1), 1 -> V1/v1 (W1)
    const int i = blockIdx.x % (NN + 1);
    const int t = threadIdx.x;
    const float* M = m ? W1 : Wr1;
    const float* src = (i < NN) ? (W0 + i * HD) : b0;
    s[t] = src[t];
    __syncthreads();
    float acc = 0.f;
#pragma unroll 8
    for (int k = 0; k < HD; ++k) acc = fmaf(s[k], M[k * HD + t], acc);
    if (i < NN) {
        (m ? g_V1 : g_U1)[i * HD + t] = acc;
    } else {
        if (m) g_v1[t] = acc;
        else   g_u1[t] = acc + br1[t];
    }
}

__global__ void pre2_kernel(const float* __restrict__ W2,
                            const float* __restrict__ Wr2,
                            const float* __restrict__ b2,
                            const float* __restrict__ br2)
{
    __shared__ float s[HD];
    const int m = blockIdx.x / (NN + 1);    // 0 -> P/p (W2), 1 -> Q/q (Wr2)
    const int i = blockIdx.x % (NN + 1);
    const int t = threadIdx.x;
    const float* M = m ? Wr2 : W2;
    const float* src = (i < NN) ? (g_U1 + i * HD) : g_u1;
    s[t] = src[t];
    __syncthreads();
    float acc = 0.f;
#pragma unroll 8
    for (int k = 0; k < HD; ++k) acc = fmaf(s[k], M[k * HD + t], acc);
    if (i < NN) {
        (m ? g_Q : g_P)[i * HD + t] = acc;
    } else {
        if (m) g_q[t] = acc + b2[t] + br2[t];
        else   g_p[t] = acc;
    }
}

// ---------------------------- packed fp32x2 helpers -------------------------
__device__ __forceinline__ u64 pack2(float a, float b) {
    u64 r; asm("mov.b64 %0, {%1, %2};" : "=l"(r) : "f"(a), "f"(b)); return r;
}
__device__ __forceinline__ void fma2(u64& d, u64 a, u64 b) {
    asm("fma.rn.f32x2 %0, %1, %2, %0;" : "+l"(d) : "l"(a), "l"(b));
}
__device__ __forceinline__ float2 unpack2(u64 v) {
    float lo, hi; asm("mov.b64 {%0, %1}, %2;" : "=f"(lo), "=f"(hi) : "l"(v));
    return make_float2(lo, hi);
}

// C[rows x 128] = S[rows x K] @ W[K x 128]; epilogue via nullable pointers
// thread map: cg = tid&31 -> 4 consecutive cols; warp covers rows [r0, r0+RPGT)
template<int K, int RPGT>
__device__ __forceinline__ void gemm_stage(
    const float* __restrict__ S, int ldS,
    const float* __restrict__ W,
    const float* __restrict__ bias,        // nullable
    const float* __restrict__ r1vec,       // nullable: + avals[r]*r1vec[c]
    const float* __restrict__ avals,
    bool relu,
    const float* __restrict__ AddSm,       // nullable: + AddSm[r][c] (stride HD)
    const float* __restrict__ AddGl,       // nullable: + AddGl[r][c] (stride HD)
    float* __restrict__ outR, int ldOutR,  // row-major out
    float* __restrict__ outT,              // nullable: also transpose (YT_LD)
    int r0)
{
    const int tid = threadIdx.x;
    const int cg = tid & 31;
    const int c0 = cg << 2;

    float4 bz = make_float4(0.f, 0.f, 0.f, 0.f);
    if (bias) bz = *(const float4*)(bias + c0);

    u64 acc[RPGT][2];
#pragma unroll
    for (int r = 0; r < RPGT; ++r) {
        acc[r][0] = pack2(bz.x, bz.y);
        acc[r][1] = pack2(bz.z, bz.w);
    }

    const float* srow[RPGT];
#pragma unroll
    for (int r = 0; r < RPGT; ++r) srow[r] = S + (r0 + r) * ldS;

    const ulonglong2* Wp = (const ulonglong2*)W + cg;   // row stride = 32 ull2

    constexpr int NITER = K / 4;
    constexpr int K4 = NITER * 4;

    ulonglong2 wv[2][4];
#pragma unroll
    for (int i = 0; i < 4; ++i) wv[0][i] = Wp[i * (HD / 4)];

#pragma unroll 2
    for (int it = 0; it < NITER; ++it) {
        const int k = it * 4;
        const int cur = it & 1;
        const int nxt = cur ^ 1;
        if (it + 1 < NITER) {
#pragma unroll
            for (int i = 0; i < 4; ++i)
                wv[nxt][i] = Wp[(k + 4 + i) * (HD / 4)];
        }
        float4 s4[RPGT];
#pragma unroll
        for (int r = 0; r < RPGT; ++r)
            s4[r] = *(const float4*)(srow[r] + k);
#pragma unroll
        for (int i = 0; i < 4; ++i) {
#pragma unroll
            for (int r = 0; r < RPGT; ++r) {
                float s = ((const float*)&s4[r])[i];
                u64 ss = pack2(s, s);
                fma2(acc[r][0], ss, wv[cur][i].x);
                fma2(acc[r][1], ss, wv[cur][i].y);
            }
        }
    }
#pragma unroll
    for (int k = K4; k < K; ++k) {
        ulonglong2 wvt = Wp[k * (HD / 4)];
#pragma unroll
        for (int r = 0; r < RPGT; ++r) {
            float s = srow[r][k];
            u64 ss = pack2(s, s);
            fma2(acc[r][0], ss, wvt.x);
            fma2(acc[r][1], ss, wvt.y);
        }
    }

    float4 r1v = make_float4(0.f, 0.f, 0.f, 0.f);
    if (r1vec) r1v = *(const float4*)(r1vec + c0);

#pragma unroll
    for (int r = 0; r < RPGT; ++r) {
        const int rr = r0 + r;
        float2 p0 = unpack2(acc[r][0]);
        float2 p1 = unpack2(acc[r][1]);
        float v0 = p0.x, v1 = p0.y, v2 = p1.x, v3 = p1.y;
        if (r1vec) {
            float av = avals[rr];
            v0 = fmaf(av, r1v.x, v0); v1 = fmaf(av, r1v.y, v1);
            v2 = fmaf(av, r1v.z, v2); v3 = fmaf(av, r1v.w, v3);
        }
        if (relu) {
            v0 = fmaxf(v0, 0.f); v1 = fmaxf(v1, 0.f);
            v2 = fmaxf(v2, 0.f); v3 = fmaxf(v3, 0.f);
        }
        if (AddSm) {
            float4 mv = *(const float4*)(AddSm + rr * HD + c0);
            v0 += mv.x; v1 += mv.y; v2 += mv.z; v3 += mv.w;
        }
        if (AddGl) {
            float4 gv = *(const float4*)(AddGl + rr * HD + c0);
            v0 += gv.x; v1 += gv.y; v2 += gv.z; v3 += gv.w;
        }
        if (outT) {
            outT[(c0 + 0) * YT_LD + rr] = v0;
            outT[(c0 + 1) * YT_LD + rr] = v1;
            outT[(c0 + 2) * YT_LD + rr] = v2;
            outT[(c0 + 3) * YT_LD + rr] = v3;
        }
        *(float4*)(outR + rr * ldOutR + c0) = make_float4(v0, v1, v2, v3);
    }
}

// Z stage, SMSP-balanced: every warp processes
//   2 NB0 rows (2w, 2w+1):     j blocks 0,1,2
//   2 NB1 rows (32+2w, 33+2w): j blocks 1,2
//   N2 NB2 rows:               j block 2 only
//     N2==2: rows 64+2w, 65+2w   (w < 10)
//     N2==1: row  84+(w-10)      (w >= 10)
template<int N2>
__device__ __forceinline__ void z_mixed(const float* __restrict__ sm,
                                        float* __restrict__ Zs,
                                        int w, int lane)
{
    const float* Yb  = sm + OFF_Y;
    const float* YTb = sm + OFF_YT;

    const int rA = 2 * w;
    const int rB = 32 + 2 * w;
    const int rC = (N2 == 2) ? (64 + 2 * w) : (84 + (w - 10));

    const float* yA0 = Yb + (rA    ) * Y_LD;
    const float* yA1 = Yb + (rA + 1) * Y_LD;
    const float* yB0 = Yb + (rB    ) * Y_LD;
    const float* yB1 = Yb + (rB + 1) * Y_LD;
    const float* yC0 = Yb + (rC    ) * Y_LD;
    const float* yC1 = Yb + (rC + (N2 - 1)) * Y_LD;   // ==yC0 when N2==1

    const bool has_j2 = lane < (NN - 64);   // lane+64 < 90

    u64 accA[2];  float accA2[2];
    u64 accB[2];
    float accC[2];
#pragma unroll
    for (int r = 0; r < 2; ++r) {
        accA[r] = 0ull; accA2[r] = 0.f; accB[r] = 0ull; accC[r] = 0.f;
    }

#pragma unroll 1
    for (int c = 0; c < HD; c += 4) {
        float4 a0 = *(const float4*)(yA0 + c);
        float4 a1 = *(const float4*)(yA1 + c);
        float4 b0 = *(const float4*)(yB0 + c);
        float4 b1 = *(const float4*)(yB1 + c);
        float4 c0v = *(const float4*)(yC0 + c);
        float4 c1v;
        if (N2 == 2) c1v = *(const float4*)(yC1 + c);
#pragma unroll
        for (int cc = 0; cc < 4; ++cc) {
            const float* yr = YTb + (c + cc) * YT_LD;
            float yj0 = yr[lane];
            float yj1 = yr[lane + 32];
            float yj2 = has_j2 ? yr[lane + 64] : 0.f;
            u64 yj01 = pack2(yj0, yj1);
            u64 yj12 = pack2(yj1, yj2);

            float ya0 = ((const float*)&a0)[cc];
            float ya1 = ((const float*)&a1)[cc];
            fma2(accA[0], pack2(ya0, ya0), yj01);
            fma2(accA[1], pack2(ya1, ya1), yj01);
            accA2[0] = fmaf(ya0, yj2, accA2[0]);
            accA2[1] = fmaf(ya1, yj2, accA2[1]);

            float yb0 = ((const float*)&b0)[cc];
            float yb1 = ((const float*)&b1)[cc];
            fma2(accB[0], pack2(yb0, yb0), yj12);
            fma2(accB[1], pack2(yb1, yb1), yj12);

            float yc0 = ((const float*)&c0v)[cc];
            accC[0] = fmaf(yc0, yj2, accC[0]);
            if (N2 == 2) {
                float yc1 = ((const float*)&c1v)[cc];
                accC[1] = fmaf(yc1, yj2, accC[1]);
            }
        }
    }

#pragma unroll
    for (int r = 0; r < 2; ++r) {
        float* zr = Zs + (rA + r) * ZS_LD;
        float2 pj = unpack2(accA[r]);
        zr[lane]      = pj.x;
        zr[lane + 32] = pj.y;
        if (has_j2) zr[lane + 64] = accA2[r];
    }
#pragma unroll
    for (int r = 0; r < 2; ++r) {
        float* zr = Zs + (rB + r) * ZS_LD;
        float2 pj = unpack2(accB[r]);
        zr[lane + 32] = pj.x;
        if (has_j2) zr[lane + 64] = pj.y;
    }
#pragma unroll
    for (int r = 0; r < N2; ++r) {
        float* zr = Zs + (rC + r) * ZS_LD;
        if (has_j2) zr[lane + 64] = accC[r];
    }
}

__global__ void __launch_bounds__(NTHREADS, 1) graphcnn_kernel(
    const float* __restrict__ adj,
    const float* __restrict__ W2g,
    const float* __restrict__ b1g,
    float* __restrict__ out)
{
    extern __shared__ float sm[];
    const int b = blockIdx.x;
    const int tid = threadIdx.x;
    const int w = tid >> 5;
    const int lane = tid & 31;
    // SMSP-balanced rows: warps 0-9 take 6 rows, warps 10-15 take 5 rows
    const int r0 = (w < 10) ? 6 * w : 60 + 5 * (w - 10);

    // load adjacency into padded [90 x 92] smem tile
    {
        const float* ag = adj + (size_t)b * (NN * NN);
#pragma unroll
        for (int i = tid; i < NN * NN; i += NTHREADS) {
            int r = i / NN;
            int c = i - r * NN;
            sm[OFF_A + r * A_LD + c] = ag[i];
        }
    }
    __syncthreads();

    // a = rowsums of A
    if (tid < NN) {
        const float* ar = sm + OFF_A + tid * A_LD;
        float s = 0.f;
#pragma unroll 10
        for (int k = 0; k < NN; ++k) s += ar[k];
        sm[OFF_AS + tid] = s;
    }

#define RUN_GEMM(KV, ...) do {                                   \
        if (w < 10) gemm_stage<KV, 6>(__VA_ARGS__, r0);          \
        else        gemm_stage<KV, 5>(__VA_ARGS__, r0);          \
    } while (0)

    // G1: B1 = A @ V1
    RUN_GEMM(NN, sm + OFF_A, A_LD, g_V1, nullptr, nullptr, nullptr, false,
             nullptr, nullptr, sm + OFF_B1, HD, nullptr);
    __syncthreads();

    // G2: R3 = relu(A @ B1 + a v1^T + 1 b1^T)
    RUN_GEMM(NN, sm + OFF_A, A_LD, sm + OFF_B1, b1g, g_v1, sm + OFF_AS, true,
             nullptr, nullptr, sm + OFF_B2, HD, nullptr);
    __syncthreads();

    // G3: M2 = R3 @ W2
    RUN_GEMM(HD, sm + OFF_B2, HD, W2g, nullptr, nullptr, nullptr, false,
             nullptr, nullptr, sm + OFF_B1, HD, nullptr);
    __syncthreads();

    // G4: C = A @ P + M2 + Q
    RUN_GEMM(NN, sm + OFF_A, A_LD, g_P, nullptr, nullptr, nullptr, false,
             sm + OFF_B1, g_Q, sm + OFF_B2, HD, nullptr);
    __syncthreads();

    // G5: Y = relu(A @ C + a p^T + 1 q^T)  -> Y (Y_LD) + YT
    RUN_GEMM(NN, sm + OFF_A, A_LD, sm + OFF_B2, g_q, g_p, sm + OFF_AS, true,
             nullptr, nullptr, sm + OFF_Y, Y_LD, sm + OFF_YT);
    __syncthreads();
#undef RUN_GEMM

    // G6: Zs[i][j] = sum_c Y[i][c] * Yt[c][j], symmetric skip, SMSP-balanced
    float* Zs = sm + OFF_A;                    // A is dead; 90*92 fits exactly
    if (w < 10) z_mixed<2>(sm, Zs, w, lane);
    else        z_mixed<1>(sm, Zs, w, lane);
    __syncthreads();

    // mirror + writeout: skipped (i,j) come from Zs[j][i]
    // row classes now exact: i<32 all blocks; 32<=i<64 blocks 1,2; i>=64 block 2
    float* ob = out + (size_t)b * (NN * NN);
#pragma unroll
    for (int idx = tid; idx < NN * NN; idx += NTHREADS) {
        int i = idx / NN;
        int j = idx - i * NN;
        int nbi = (i >= 64) ? 2 : (i >= 32 ? 1 : 0);
        bool avail = (j >> 5) >= nbi;
        ob[idx] = avail ? Zs[i * ZS_LD + j] : Zs[j * ZS_LD + i];
    }
}

extern "C" void kernel_launch(void* const* d_in, const int* in_sizes, int n_in,
                              void* d_out, int out_size) {
    const float* adj = (const float*)d_in[0];
    const float* W0  = (const float*)d_in[1];
    const float* b0  = (const float*)d_in[2];
    const float* W1  = (const float*)d_in[3];
    const float* b1  = (const float*)d_in[4];
    const float* W2  = (const float*)d_in[5];
    const float* b2  = (const float*)d_in[6];
    const float* Wr1 = (const float*)d_in[7];
    const float* br1 = (const float*)d_in[8];
    const float* Wr2 = (const float*)d_in[9];
    const float* br2 = (const float*)d_in[10];
    float* out = (float*)d_out;

    const int B = in_sizes[0] / (NN * NN);
    const size_t smem = SMEM_FLOATS * sizeof(float);   // 219,776 B

    pre1_kernel<<<2 * (NN + 1), HD>>>(W0, Wr1, W1, b0, br1);
    pre2_kernel<<<2 * (NN + 1), HD>>>(W2, Wr2, b2, br2);

    cudaFuncSetAttribute(graphcnn_kernel,
                         cudaFuncAttributeMaxDynamicSharedMemorySize, (int)smem);
    graphcnn_kernel<<<B, NTHREADS, smem>>>(adj, W2, b1, out);
}